// round 16
// baseline (speedup 1.0000x reference)
#include <cuda_runtime.h>
#include <cuda_fp16.h>
#include <cstdint>

#define BATCH    8
#define CDIM     512
#define NPOS     2048
#define HEADS    8
#define DIM_HEAD 64
#define HIDDEN   512
#define QKV_ROWS 1536
#define EPS_LN   1e-5f

/* ---------------- scratch (static device globals) ---------------- */
__device__ uint32_t g_xnh[BATCH * 256 * NPOS];       /* LN out half2 [b][cp][n]     */
__device__ uint32_t g_aoh[BATCH * 256 * NPOS];       /* attn out half2 [b][kp][n]   */
__device__ uint32_t g_wqh[256 * QKV_ROWS];           /* W_qkv half2 [kp][M]         */
__device__ uint32_t g_woh[256 * CDIM];               /* W_out half2 [kp][M]         */
/* Q/K: [bh][dp][block(n/64)][pos]  pos = (jl&7)*8 + (jl>>3)  (fragment-major) */
__device__ uint32_t g_qpk[64 * 32 * 2048];
__device__ uint32_t g_kpk[64 * 32 * 2048];
/* V: [bh][jp][pos(d)]  same permutation on d */
__device__ uint32_t g_vpk[64 * 1024 * 64];

/* ---------------- helpers ---------------- */
__device__ __forceinline__ uint32_t f2tf(float f) {
    uint32_t u;
    asm("cvt.rna.tf32.f32 %0, %1;" : "=r"(u) : "f"(f));
    return u;
}
__device__ __forceinline__ float tfr(float f) { return __uint_as_float(f2tf(f)); }
__device__ __forceinline__ uint32_t pk_h2(float lo, float hi) {
    __half2 h = __floats2half2_rn(lo, hi);
    return *(uint32_t*)&h;
}
__device__ __forceinline__ void mma_f16(float& c0, float& c1, float& c2, float& c3,
                                        uint32_t a0, uint32_t a1, uint32_t a2, uint32_t a3,
                                        uint32_t b0, uint32_t b1) {
    asm("mma.sync.aligned.m16n8k16.row.col.f32.f16.f16.f32 "
        "{%0,%1,%2,%3},{%4,%5,%6,%7},{%8,%9},{%0,%1,%2,%3};"
        : "+f"(c0), "+f"(c1), "+f"(c2), "+f"(c3)
        : "r"(a0), "r"(a1), "r"(a2), "r"(a3), "r"(b0), "r"(b1));
}
__device__ __forceinline__ void cpasync16(uint32_t dst, const void* src) {
    asm volatile("cp.async.cg.shared.global [%0], [%1], 16;" :: "r"(dst), "l"(src));
}
#define CP_COMMIT() asm volatile("cp.async.commit_group;")
#define CP_WAIT(n)  asm volatile("cp.async.wait_group %0;" :: "n"(n))

/* =====================================================================
 * Kernel 0: one-time weight prepack (tf32-round -> half2 [kp][M])
 * ===================================================================== */
__global__ void pack_w(const float* __restrict__ src, uint32_t* __restrict__ dst,
                       int M, int K) {
    int lin = blockIdx.x * 256 + threadIdx.x;
    int kp = lin % (K >> 1);
    int m  = lin / (K >> 1);
    float a = tfr(src[(long)m * K + 2 * kp]);
    float b = tfr(src[(long)m * K + 2 * kp + 1]);
    dst[(long)kp * M + m] = pk_h2(a, b);
}

/* =====================================================================
 * Kernel 1: channel LayerNorm -> packed half2 [b][cp][n]  (verbatim)
 * ===================================================================== */
__global__ void __launch_bounds__(512)
ln_kernel(const float* __restrict__ x,
          const float* __restrict__ g,
          uint32_t* __restrict__ xnh) {
    __shared__ float gs[CDIM];
    __shared__ float red[2][8][64];
    int t = threadIdx.x;
    if (t < CDIM) gs[t] = g[t];

    int nl = t & 63;
    int cs = t >> 6;
    int pos0 = blockIdx.x * 64;
    int b  = pos0 / NPOS;
    int n0 = pos0 % NPOS;

    const float* xp = x + (long)b * CDIM * NPOS + n0 + nl;
    float s = 0.f, ss = 0.f;
    #pragma unroll 8
    for (int c = cs * 64; c < cs * 64 + 64; c++) {
        float v = xp[(long)c * NPOS];
        s += v; ss += v * v;
    }
    red[0][cs][nl] = s;  red[1][cs][nl] = ss;
    __syncthreads();
    float st = 0.f, sst = 0.f;
    #pragma unroll
    for (int k = 0; k < 8; k++) { st += red[0][k][nl]; sst += red[1][k][nl]; }
    float mean = st * (1.f / CDIM);
    float inv  = rsqrtf(sst * (1.f / CDIM) - mean * mean + EPS_LN);

    uint32_t* op = xnh + (long)b * 256 * NPOS + n0 + nl;
    #pragma unroll 8
    for (int c = cs * 64; c < cs * 64 + 64; c += 2) {
        float v0 = tfr((xp[(long)(c + 0) * NPOS] - mean) * inv * gs[c + 0]);
        float v1 = tfr((xp[(long)(c + 1) * NPOS] - mean) * inv * gs[c + 1]);
        op[(long)(c >> 1) * NPOS] = pk_h2(v0, v1);
    }
}

/* =====================================================================
 * FP16 GEMM mainloop (R13/14 proven)
 * ===================================================================== */
#define FASTG (16 * 136)
#define GEMM16_SMEM (3 * 2 * FASTG * 4)

#define GEMM_MAINLOOP(ACC)                                                      \
    const int NIT = K / 32;                                                     \
    auto load_stage = [&](int buf, int kp0) {                                   \
        _Pragma("unroll")                                                       \
        for (int ss = 0; ss < 2; ss++) {                                        \
            int c = ss * 256 + t;                                               \
            int row = c >> 5, cw = (c & 31) << 2;                               \
            cpasync16(sbase + (buf * FASTG + row * 136 + cw) * 4,               \
                      Ab + (long)(kp0 + row) * M + cw);                         \
        }                                                                       \
        _Pragma("unroll")                                                       \
        for (int ss = 0; ss < 2; ss++) {                                        \
            int c = ss * 256 + t;                                               \
            int row = c >> 5, cw = (c & 31) << 2;                               \
            cpasync16(sbase + ((3 + buf) * FASTG + row * 136 + cw) * 4,         \
                      Bb + (long)(kp0 + row) * NPOS + cw);                      \
        }                                                                       \
        CP_COMMIT();                                                            \
    };                                                                          \
    load_stage(0, 0);                                                           \
    if (NIT > 1) load_stage(1, 16);                                             \
    for (int it = 0; it < NIT; it++) {                                          \
        if (it + 1 < NIT) { CP_WAIT(1); } else { CP_WAIT(0); }                  \
        __syncthreads();                                                        \
        if (it + 2 < NIT) load_stage((it + 2) % 3, (it + 2) * 16);              \
        const uint32_t* Ab_s = gsm + (it % 3) * FASTG;                          \
        const uint32_t* Bb_s = gsm + (3 + it % 3) * FASTG;                      \
        _Pragma("unroll")                                                       \
        for (int kb = 0; kb < 2; kb++) {                                        \
            int kr0 = (kb * 8 + tg) * 136;                                      \
            int kr1 = (kb * 8 + 4 + tg) * 136;                                  \
            uint32_t af[4][4];                                                  \
            _Pragma("unroll")                                                   \
            for (int mt = 0; mt < 4; mt++) {                                    \
                int r = wm + mt * 16 + g;                                       \
                af[mt][0] = Ab_s[kr0 + r];                                      \
                af[mt][1] = Ab_s[kr0 + r + 8];                                  \
                af[mt][2] = Ab_s[kr1 + r];                                      \
                af[mt][3] = Ab_s[kr1 + r + 8];                                  \
            }                                                                   \
            uint32_t bf[4][2];                                                  \
            _Pragma("unroll")                                                   \
            for (int nt = 0; nt < 4; nt++) {                                    \
                int c = wn + nt * 8 + g;                                        \
                bf[nt][0] = Bb_s[kr0 + c];                                      \
                bf[nt][1] = Bb_s[kr1 + c];                                      \
            }                                                                   \
            _Pragma("unroll")                                                   \
            for (int mt = 0; mt < 4; mt++)                                      \
                _Pragma("unroll")                                               \
                for (int nt = 0; nt < 4; nt++)                                  \
                    mma_f16(ACC[mt][nt][0], ACC[mt][nt][1],                     \
                            ACC[mt][nt][2], ACC[mt][nt][3],                     \
                            af[mt][0], af[mt][1], af[mt][2], af[mt][3],         \
                            bf[nt][0], bf[nt][1]);                              \
        }                                                                       \
    }

/* =====================================================================
 * Kernel 2: QKV projection, fused pack epilogue -> PERMUTED layouts.
 * Same values as R15 (bitwise); only store positions changed.
 * ===================================================================== */
__global__ void __launch_bounds__(256, 2)
gemm_qkv(const uint32_t* __restrict__ Ah, const uint32_t* __restrict__ Bh,
         uint32_t* __restrict__ qpk, uint32_t* __restrict__ kpk,
         uint32_t* __restrict__ vpk, int M, int K) {
    extern __shared__ uint32_t gsm[];
    int t = threadIdx.x, lane = t & 31, w = t >> 5;
    int m0 = blockIdx.x * 128, n0 = blockIdx.y * 128, b = blockIdx.z;
    const uint32_t* Ab = Ah + m0;
    const uint32_t* Bb = Bh + (long)b * (K >> 1) * NPOS + n0;
    uint32_t sbase = (uint32_t)__cvta_generic_to_shared(gsm);

    int wm = (w >> 2) * 64;
    int wn = (w & 3) * 32;
    int g  = lane >> 2, tg = lane & 3;

    float acc[4][4][4];
    #pragma unroll
    for (int i = 0; i < 4; i++)
        #pragma unroll
        for (int j = 0; j < 4; j++)
            #pragma unroll
            for (int r = 0; r < 4; r++) acc[i][j][r] = 0.f;

    GEMM_MAINLOOP(acc)

    int part = m0 >> 9;
    float qs = (part == 0) ? 0.125f : 1.0f;
    bool evg = (g & 1) == 0;

    #pragma unroll
    for (int mt = 0; mt < 4; mt++) {
        int row0 = m0 + wm + mt * 16 + g;
        int h  = (row0 & 511) >> 6;
        int bh = b * 8 + h;
        #pragma unroll
        for (int nt = 0; nt < 4; nt++) {
            int c0 = n0 + wn + nt * 8 + 2 * tg;
            float v0 = tfr(acc[mt][nt][0]) * qs;
            float v1 = tfr(acc[mt][nt][1]) * qs;
            float v2 = tfr(acc[mt][nt][2]) * qs;
            float v3 = tfr(acc[mt][nt][3]) * qs;
            if (part < 2) {
                float p0 = __shfl_xor_sync(0xffffffffu, v0, 4);
                float p1 = __shfl_xor_sync(0xffffffffu, v1, 4);
                float p2 = __shfl_xor_sync(0xffffffffu, v2, 4);
                float p3 = __shfl_xor_sync(0xffffffffu, v3, 4);
                if (evg) {
                    int dp = (row0 & 63) >> 1;
                    int jl = c0 & 63;
                    int pos = ((jl & 7) << 3) + (jl >> 3);   /* fragment-major */
                    uint32_t* dst = (part == 0 ? qpk : kpk)
                                  + ((long)bh * 32 + dp) * 2048 + (c0 >> 6) * 64;
                    dst[pos]     = pk_h2(v0, p0);
                    dst[pos + 8] = pk_h2(v1, p1);            /* j+1 -> pos+8 */
                    uint32_t* dst4 = dst + 4 * 2048;         /* dp+4 */
                    dst4[pos]     = pk_h2(v2, p2);
                    dst4[pos + 8] = pk_h2(v3, p3);
                }
            } else {
                int d0 = row0 & 63;                          /* d0&7 == g */
                int posd = ((d0 & 7) << 3) + (d0 >> 3);      /* d0+8 -> posd+1 */
                int jp = c0 >> 1;
                uint32_t* dst = vpk + ((long)bh * 1024 + jp) * 64 + posd;
                *(uint2*)dst = make_uint2(pk_h2(v0, v1), pk_h2(v2, v3));
            }
        }
    }
}

/* =====================================================================
 * Kernel 4: output projection (R14 verbatim)
 * ===================================================================== */
__global__ void __launch_bounds__(256, 2)
gemm_f16(const uint32_t* __restrict__ Ah, const uint32_t* __restrict__ Bh,
         float* __restrict__ C, const float* __restrict__ bias,
         int M, int K) {
    extern __shared__ uint32_t gsm[];
    int t = threadIdx.x, lane = t & 31, w = t >> 5;
    int m0 = blockIdx.x * 128, n0 = blockIdx.y * 128, b = blockIdx.z;
    const uint32_t* Ab = Ah + m0;
    const uint32_t* Bb = Bh + (long)b * (K >> 1) * NPOS + n0;
    float*           Cb = C  + (long)b * M * NPOS;
    uint32_t sbase = (uint32_t)__cvta_generic_to_shared(gsm);

    int wm = (w >> 2) * 64;
    int wn = (w & 3) * 32;
    int g  = lane >> 2, tg = lane & 3;

    float acc[4][4][4];
    #pragma unroll
    for (int i = 0; i < 4; i++)
        #pragma unroll
        for (int j = 0; j < 4; j++)
            #pragma unroll
            for (int r = 0; r < 4; r++) acc[i][j][r] = 0.f;

    GEMM_MAINLOOP(acc)

    #pragma unroll
    for (int mt = 0; mt < 4; mt++) {
        int r0 = m0 + wm + mt * 16 + g;
        float b0 = bias ? bias[r0]     : 0.f;
        float b1 = bias ? bias[r0 + 8] : 0.f;
        #pragma unroll
        for (int nt = 0; nt < 4; nt++) {
            int c0 = n0 + wn + nt * 8 + 2 * tg;
            *(float2*)(Cb + (long)r0 * NPOS + c0) =
                make_float2(acc[mt][nt][0] + b0, acc[mt][nt][1] + b0);
            *(float2*)(Cb + (long)(r0 + 8) * NPOS + c0) =
                make_float2(acc[mt][nt][2] + b1, acc[mt][nt][3] + b1);
        }
    }
}

/* =====================================================================
 * Kernel 3: fused FP16 flash attention — fragment-major layouts:
 *  K/V fragment loads via uint4 (2 per row), P via uint2, Q gather uint2.
 *  Structure/sync identical to R15 (proven); values bit-identical.
 * smem: KH[2][2304] VH[2][2304] PH[2304] = 46080 B -> 4 CTAs/SM.
 * ===================================================================== */
#define HST 72
#define KH_OFF 0
#define VH_OFF (2 * 2304)
#define PH_OFF (4 * 2304)
#define ATTN_SMEM_WORDS (5 * 2304)

__global__ void __launch_bounds__(128, 4)
attn_f16(const uint32_t* __restrict__ qpk, const uint32_t* __restrict__ kpk,
         const uint32_t* __restrict__ vpk, uint32_t* __restrict__ aoh) {
    extern __shared__ uint32_t sm4[];
    uint32_t* PH = sm4 + PH_OFF;
    uint32_t sbase = (uint32_t)__cvta_generic_to_shared(sm4);

    int t = threadIdx.x, lane = t & 31, w = t >> 5;
    int g = lane >> 2, tg = lane & 3;
    int iw = w * 16;

    int qt = blockIdx.x;
    int bh = blockIdx.y;
    int b  = bh >> 3, h = bh & 7;
    int i0 = qt * 64;
    int g8w = g * 8 + 2 * w;               /* permuted pos of i=iw+g; +8 -> +1 */

    const uint32_t* qb = qpk + (long)bh * 32 * 2048;
    const uint32_t* kb = kpk + (long)bh * 32 * 2048;
    const uint32_t* vb = vpk + (long)bh * 1024 * 64;

    auto load_kv = [&](int j0, int p) {
        #pragma unroll
        for (int ss = 0; ss < 4; ss++) {
            int c = ss * 128 + t;
            int dp = c >> 4, cw = (c & 15) << 2;
            cpasync16(sbase + (KH_OFF + p * 2304 + dp * HST + cw) * 4,
                      kb + (long)dp * 2048 + j0 + cw);
        }
        #pragma unroll
        for (int ss = 0; ss < 4; ss++) {
            int c = ss * 128 + t;
            int jp = c >> 4, cw = (c & 15) << 2;
            cpasync16(sbase + (VH_OFF + p * 2304 + jp * HST + cw) * 4,
                      vb + ((long)(j0 >> 1) + jp) * 64 + cw);
        }
        CP_COMMIT();
    };

    load_kv(0, 0);
    load_kv(64, 1);

    /* Q fragments: uint2 gathers from the permuted layout (one-time) */
    uint32_t aq[4][4];
    {
        int qcol = i0 + g8w;
        #pragma unroll
        for (int kbk = 0; kbk < 4; kbk++) {
            uint2 qa = *(const uint2*)(qb + (long)(kbk * 8 + tg) * 2048 + qcol);
            uint2 qc = *(const uint2*)(qb + (long)(kbk * 8 + 4 + tg) * 2048 + qcol);
            aq[kbk][0] = qa.x; aq[kbk][1] = qa.y;
            aq[kbk][2] = qc.x; aq[kbk][3] = qc.y;
        }
    }

    float m_s[2], l_s[2];
    float o[8][4];
    m_s[0] = m_s[1] = -1e30f;
    l_s[0] = l_s[1] = 0.f;
    #pragma unroll
    for (int nt = 0; nt < 8; nt++)
        #pragma unroll
        for (int r = 0; r < 4; r++) o[nt][r] = 0.f;

    const int T = NPOS / 64;
    for (int ti = 0; ti < T; ti++) {
        int p = ti & 1;
        if (ti + 1 < T) { CP_WAIT(1); } else { CP_WAIT(0); }
        __syncthreads();

        const uint32_t* KH = sm4 + KH_OFF + p * 2304;
        const uint32_t* VH = sm4 + VH_OFF + p * 2304;

        /* ---- S = Q^T K : wide fragment loads ---- */
        float sa[8][4];
        #pragma unroll
        for (int nt = 0; nt < 8; nt++)
            #pragma unroll
            for (int r = 0; r < 4; r++) sa[nt][r] = 0.f;

        #pragma unroll
        for (int kbk = 0; kbk < 4; kbk++) {
            int rlo = (kbk * 8 + tg) * HST + g * 8;
            int rhi = (kbk * 8 + 4 + tg) * HST + g * 8;
            uint4 kA = *(const uint4*)&KH[rlo];
            uint4 kB = *(const uint4*)&KH[rlo + 4];
            uint4 kC = *(const uint4*)&KH[rhi];
            uint4 kD = *(const uint4*)&KH[rhi + 4];
            uint32_t b0s[8] = {kA.x, kA.y, kA.z, kA.w, kB.x, kB.y, kB.z, kB.w};
            uint32_t b1s[8] = {kC.x, kC.y, kC.z, kC.w, kD.x, kD.y, kD.z, kD.w};
            #pragma unroll
            for (int nt = 0; nt < 8; nt++)
                mma_f16(sa[nt][0], sa[nt][1], sa[nt][2], sa[nt][3],
                        aq[kbk][0], aq[kbk][1], aq[kbk][2], aq[kbk][3],
                        b0s[nt], b1s[nt]);
        }

        /* ---- online softmax (R15 numerics verbatim; uint2 P store) ---- */
        {
            float mx0 = -1e30f, mx1 = -1e30f;
            #pragma unroll
            for (int nt = 0; nt < 8; nt++) {
                mx0 = fmaxf(mx0, fmaxf(sa[nt][0], sa[nt][1]));
                mx1 = fmaxf(mx1, fmaxf(sa[nt][2], sa[nt][3]));
            }
            mx0 = fmaxf(mx0, __shfl_xor_sync(0xffffffffu, mx0, 1));
            mx0 = fmaxf(mx0, __shfl_xor_sync(0xffffffffu, mx0, 2));
            mx1 = fmaxf(mx1, __shfl_xor_sync(0xffffffffu, mx1, 1));
            mx1 = fmaxf(mx1, __shfl_xor_sync(0xffffffffu, mx1, 2));
            float mn0 = fmaxf(m_s[0], mx0);
            float mn1 = fmaxf(m_s[1], mx1);
            float s0 = 0.f, s1 = 0.f;
            #pragma unroll
            for (int nt = 0; nt < 8; nt++) {
                float p0 = __expf(sa[nt][0] - mn0);
                float p1 = __expf(sa[nt][1] - mn0);
                float p2 = __expf(sa[nt][2] - mn1);
                float p3 = __expf(sa[nt][3] - mn1);
                s0 += p0 + p1;  s1 += p2 + p3;
                int jp = nt * 4 + tg;
                *(uint2*)&PH[jp * HST + g8w] =
                    make_uint2(pk_h2(p0, p1), pk_h2(p2, p3));
            }
            s0 += __shfl_xor_sync(0xffffffffu, s0, 1);
            s0 += __shfl_xor_sync(0xffffffffu, s0, 2);
            s1 += __shfl_xor_sync(0xffffffffu, s1, 1);
            s1 += __shfl_xor_sync(0xffffffffu, s1, 2);
            float al0 = __expf(m_s[0] - mn0);
            float al1 = __expf(m_s[1] - mn1);
            l_s[0] = l_s[0] * al0 + s0;  m_s[0] = mn0;
            l_s[1] = l_s[1] * al1 + s1;  m_s[1] = mn1;
            #pragma unroll
            for (int nt = 0; nt < 8; nt++) {
                o[nt][0] *= al0; o[nt][1] *= al0;
                o[nt][2] *= al1; o[nt][3] *= al1;
            }
        }
        __syncwarp();

        /* ---- O += P V^T : wide fragment loads ---- */
        #pragma unroll
        for (int jb = 0; jb < 4; jb++) {
            int rlo = (jb * 8 + tg) * HST;
            int rhi = (jb * 8 + 4 + tg) * HST;
            uint2 pa01 = *(const uint2*)&PH[rlo + g8w];
            uint2 pa23 = *(const uint2*)&PH[rhi + g8w];
            uint4 vA = *(const uint4*)&VH[rlo + g * 8];
            uint4 vB = *(const uint4*)&VH[rlo + g * 8 + 4];
            uint4 vC = *(const uint4*)&VH[rhi + g * 8];
            uint4 vD = *(const uint4*)&VH[rhi + g * 8 + 4];
            uint32_t b0s[8] = {vA.x, vA.y, vA.z, vA.w, vB.x, vB.y, vB.z, vB.w};
            uint32_t b1s[8] = {vC.x, vC.y, vC.z, vC.w, vD.x, vD.y, vD.z, vD.w};
            #pragma unroll
            for (int nt = 0; nt < 8; nt++)
                mma_f16(o[nt][0], o[nt][1], o[nt][2], o[nt][3],
                        pa01.x, pa01.y, pa23.x, pa23.y,
                        b0s[nt], b1s[nt]);
        }
        __syncthreads();
        if (ti + 2 < T) load_kv((ti + 2) * 64, p);
    }

    /* ---- epilogue: normalize, tf32-round, transpose via retired smem ---- */
    {
        float inv0 = 1.f / l_s[0], inv1 = 1.f / l_s[1];
        int r0 = iw + g;
        #pragma unroll
        for (int nt = 0; nt < 8; nt++) {
            int d0 = nt * 8 + 2 * tg;
            sm4[d0 * 68 + r0]           = f2tf(o[nt][0] * inv0);
            sm4[(d0 + 1) * 68 + r0]     = f2tf(o[nt][1] * inv0);
            sm4[d0 * 68 + r0 + 8]       = f2tf(o[nt][2] * inv1);
            sm4[(d0 + 1) * 68 + r0 + 8] = f2tf(o[nt][3] * inv1);
        }
    }
    __syncthreads();
    uint32_t* aop = aoh + ((long)b * 256 + (long)h * 32) * NPOS + i0;
    #pragma unroll
    for (int ss = 0; ss < 4; ss++) {
        int lin = ss * 128 + t;
        int dp = lin >> 4, i4 = (lin & 15) << 2;
        uint4 wv;
        wv.x = pk_h2(__uint_as_float(sm4[(2 * dp) * 68 + i4 + 0]),
                     __uint_as_float(sm4[(2 * dp + 1) * 68 + i4 + 0]));
        wv.y = pk_h2(__uint_as_float(sm4[(2 * dp) * 68 + i4 + 1]),
                     __uint_as_float(sm4[(2 * dp + 1) * 68 + i4 + 1]));
        wv.z = pk_h2(__uint_as_float(sm4[(2 * dp) * 68 + i4 + 2]),
                     __uint_as_float(sm4[(2 * dp + 1) * 68 + i4 + 2]));
        wv.w = pk_h2(__uint_as_float(sm4[(2 * dp) * 68 + i4 + 3]),
                     __uint_as_float(sm4[(2 * dp + 1) * 68 + i4 + 3]));
        *(uint4*)(aop + (long)dp * NPOS + i4) = wv;
    }
}

/* ===================================================================== */
extern "C" void kernel_launch(void* const* d_in, const int* in_sizes, int n_in,
                              void* d_out, int out_size) {
    const float* x    = (const float*)d_in[0];
    const float* g    = (const float*)d_in[1];
    const float* Wqkv = (const float*)d_in[2];
    const float* Wout = (const float*)d_in[3];
    const float* bout = (const float*)d_in[4];
    float* out = (float*)d_out;

    uint32_t *xnh, *aoh, *wqh, *woh, *qpk, *kpk, *vpk;
    cudaGetSymbolAddress((void**)&xnh, g_xnh);
    cudaGetSymbolAddress((void**)&aoh, g_aoh);
    cudaGetSymbolAddress((void**)&wqh, g_wqh);
    cudaGetSymbolAddress((void**)&woh, g_woh);
    cudaGetSymbolAddress((void**)&qpk, g_qpk);
    cudaGetSymbolAddress((void**)&kpk, g_kpk);
    cudaGetSymbolAddress((void**)&vpk, g_vpk);

    /* 0. one-time weight prepack */
    pack_w<<<(QKV_ROWS * 256) / 256, 256>>>(Wqkv, wqh, QKV_ROWS, CDIM);
    pack_w<<<(CDIM * 256) / 256, 256>>>(Wout, woh, CDIM, HIDDEN);

    /* 1. LayerNorm -> packed half2 */
    ln_kernel<<<(BATCH * NPOS) / 64, 512>>>(x, g, xnh);

    /* 2. QKV projection with fused permuted-pack epilogue */
    cudaFuncSetAttribute(gemm_qkv,
                         cudaFuncAttributeMaxDynamicSharedMemorySize, GEMM16_SMEM);
    gemm_qkv<<<dim3(QKV_ROWS / 128, NPOS / 128, BATCH), 256, GEMM16_SMEM>>>(
        wqh, xnh, qpk, kpk, vpk, QKV_ROWS, CDIM);

    /* 3. fused fp16 attention (wide fragment loads) */
    size_t smem = ATTN_SMEM_WORDS * sizeof(uint32_t);   /* 46080 B */
    cudaFuncSetAttribute(attn_f16,
                         cudaFuncAttributeMaxDynamicSharedMemorySize, (int)smem);
    attn_f16<<<dim3(NPOS / 64, BATCH * HEADS), 128, smem>>>(qpk, kpk, vpk, aoh);

    /* 4. output projection + bias (fp32 out) */
    cudaFuncSetAttribute(gemm_f16,
                         cudaFuncAttributeMaxDynamicSharedMemorySize, GEMM16_SMEM);
    gemm_f16<<<dim3(HIDDEN / 128, NPOS / 128, BATCH), 256, GEMM16_SMEM>>>(
        woh, aoh, out, bout, HIDDEN, CDIM);
}

// round 17
// speedup vs baseline: 1.4531x; 1.4531x over previous
#include <cuda_runtime.h>
#include <cuda_fp16.h>
#include <cstdint>

#define BATCH    8
#define CDIM     512
#define NPOS     2048
#define HEADS    8
#define DIM_HEAD 64
#define HIDDEN   512
#define QKV_ROWS 1536
#define EPS_LN   1e-5f

/* ---------------- scratch (static device globals) ---------------- */
__device__ uint32_t g_xnh[BATCH * 256 * NPOS];       /* LN out half2 [b][cp][n]     */
__device__ uint32_t g_aoh[BATCH * 256 * NPOS];       /* attn out half2 [b][kp][n]   */
__device__ uint32_t g_wqh[256 * QKV_ROWS];           /* W_qkv half2 [kp][M]         */
__device__ uint32_t g_woh[256 * CDIM];               /* W_out half2 [kp][M]         */
__device__ uint32_t g_qpk[64 * 32 * 2048];           /* Q half2 d-pairs [bh][dp][n] */
__device__ uint32_t g_kpk[64 * 32 * 2048];           /* K half2 d-pairs [bh][dp][n] */
__device__ uint32_t g_vpk[64 * 1024 * 64];           /* V half2 j-pairs [bh][jp][d] */

/* ---------------- helpers ---------------- */
__device__ __forceinline__ uint32_t f2tf(float f) {
    uint32_t u;
    asm("cvt.rna.tf32.f32 %0, %1;" : "=r"(u) : "f"(f));
    return u;
}
__device__ __forceinline__ float tfr(float f) { return __uint_as_float(f2tf(f)); }
__device__ __forceinline__ uint32_t pk_h2(float lo, float hi) {
    __half2 h = __floats2half2_rn(lo, hi);
    return *(uint32_t*)&h;
}
__device__ __forceinline__ void mma_f16(float& c0, float& c1, float& c2, float& c3,
                                        uint32_t a0, uint32_t a1, uint32_t a2, uint32_t a3,
                                        uint32_t b0, uint32_t b1) {
    asm("mma.sync.aligned.m16n8k16.row.col.f32.f16.f16.f32 "
        "{%0,%1,%2,%3},{%4,%5,%6,%7},{%8,%9},{%0,%1,%2,%3};"
        : "+f"(c0), "+f"(c1), "+f"(c2), "+f"(c3)
        : "r"(a0), "r"(a1), "r"(a2), "r"(a3), "r"(b0), "r"(b1));
}
__device__ __forceinline__ void cpasync16(uint32_t dst, const void* src) {
    asm volatile("cp.async.cg.shared.global [%0], [%1], 16;" :: "r"(dst), "l"(src));
}
#define CP_COMMIT() asm volatile("cp.async.commit_group;")
#define CP_WAIT(n)  asm volatile("cp.async.wait_group %0;" :: "n"(n))

/* =====================================================================
 * Kernel 0: one-time weight prepack (tf32-round -> half2 [kp][M])
 * ===================================================================== */
__global__ void pack_w(const float* __restrict__ src, uint32_t* __restrict__ dst,
                       int M, int K) {
    int lin = blockIdx.x * 256 + threadIdx.x;
    int kp = lin % (K >> 1);
    int m  = lin / (K >> 1);
    float a = tfr(src[(long)m * K + 2 * kp]);
    float b = tfr(src[(long)m * K + 2 * kp + 1]);
    dst[(long)kp * M + m] = pk_h2(a, b);
}

/* =====================================================================
 * Kernel 1: channel LayerNorm -> packed half2 [b][cp][n]  (R15 verbatim)
 * ===================================================================== */
__global__ void __launch_bounds__(512)
ln_kernel(const float* __restrict__ x,
          const float* __restrict__ g,
          uint32_t* __restrict__ xnh) {
    __shared__ float gs[CDIM];
    __shared__ float red[2][8][64];
    int t = threadIdx.x;
    if (t < CDIM) gs[t] = g[t];

    int nl = t & 63;
    int cs = t >> 6;
    int pos0 = blockIdx.x * 64;
    int b  = pos0 / NPOS;
    int n0 = pos0 % NPOS;

    const float* xp = x + (long)b * CDIM * NPOS + n0 + nl;
    float s = 0.f, ss = 0.f;
    #pragma unroll 8
    for (int c = cs * 64; c < cs * 64 + 64; c++) {
        float v = xp[(long)c * NPOS];
        s += v; ss += v * v;
    }
    red[0][cs][nl] = s;  red[1][cs][nl] = ss;
    __syncthreads();
    float st = 0.f, sst = 0.f;
    #pragma unroll
    for (int k = 0; k < 8; k++) { st += red[0][k][nl]; sst += red[1][k][nl]; }
    float mean = st * (1.f / CDIM);
    float inv  = rsqrtf(sst * (1.f / CDIM) - mean * mean + EPS_LN);

    uint32_t* op = xnh + (long)b * 256 * NPOS + n0 + nl;
    #pragma unroll 8
    for (int c = cs * 64; c < cs * 64 + 64; c += 2) {
        float v0 = tfr((xp[(long)(c + 0) * NPOS] - mean) * inv * gs[c + 0]);
        float v1 = tfr((xp[(long)(c + 1) * NPOS] - mean) * inv * gs[c + 1]);
        op[(long)(c >> 1) * NPOS] = pk_h2(v0, v1);
    }
}

/* =====================================================================
 * FP16 GEMM mainloop (R13/14 proven)
 * ===================================================================== */
#define FASTG (16 * 136)
#define GEMM16_SMEM (3 * 2 * FASTG * 4)

#define GEMM_MAINLOOP(ACC)                                                      \
    const int NIT = K / 32;                                                     \
    auto load_stage = [&](int buf, int kp0) {                                   \
        _Pragma("unroll")                                                       \
        for (int ss = 0; ss < 2; ss++) {                                        \
            int c = ss * 256 + t;                                               \
            int row = c >> 5, cw = (c & 31) << 2;                               \
            cpasync16(sbase + (buf * FASTG + row * 136 + cw) * 4,               \
                      Ab + (long)(kp0 + row) * M + cw);                         \
        }                                                                       \
        _Pragma("unroll")                                                       \
        for (int ss = 0; ss < 2; ss++) {                                        \
            int c = ss * 256 + t;                                               \
            int row = c >> 5, cw = (c & 31) << 2;                               \
            cpasync16(sbase + ((3 + buf) * FASTG + row * 136 + cw) * 4,         \
                      Bb + (long)(kp0 + row) * NPOS + cw);                      \
        }                                                                       \
        CP_COMMIT();                                                            \
    };                                                                          \
    load_stage(0, 0);                                                           \
    if (NIT > 1) load_stage(1, 16);                                             \
    for (int it = 0; it < NIT; it++) {                                          \
        if (it + 1 < NIT) { CP_WAIT(1); } else { CP_WAIT(0); }                  \
        __syncthreads();                                                        \
        if (it + 2 < NIT) load_stage((it + 2) % 3, (it + 2) * 16);              \
        const uint32_t* Ab_s = gsm + (it % 3) * FASTG;                          \
        const uint32_t* Bb_s = gsm + (3 + it % 3) * FASTG;                      \
        _Pragma("unroll")                                                       \
        for (int kb = 0; kb < 2; kb++) {                                        \
            int kr0 = (kb * 8 + tg) * 136;                                      \
            int kr1 = (kb * 8 + 4 + tg) * 136;                                  \
            uint32_t af[4][4];                                                  \
            _Pragma("unroll")                                                   \
            for (int mt = 0; mt < 4; mt++) {                                    \
                int r = wm + mt * 16 + g;                                       \
                af[mt][0] = Ab_s[kr0 + r];                                      \
                af[mt][1] = Ab_s[kr0 + r + 8];                                  \
                af[mt][2] = Ab_s[kr1 + r];                                      \
                af[mt][3] = Ab_s[kr1 + r + 8];                                  \
            }                                                                   \
            uint32_t bf[4][2];                                                  \
            _Pragma("unroll")                                                   \
            for (int nt = 0; nt < 4; nt++) {                                    \
                int c = wn + nt * 8 + g;                                        \
                bf[nt][0] = Bb_s[kr0 + c];                                      \
                bf[nt][1] = Bb_s[kr1 + c];                                      \
            }                                                                   \
            _Pragma("unroll")                                                   \
            for (int mt = 0; mt < 4; mt++)                                      \
                _Pragma("unroll")                                               \
                for (int nt = 0; nt < 4; nt++)                                  \
                    mma_f16(ACC[mt][nt][0], ACC[mt][nt][1],                     \
                            ACC[mt][nt][2], ACC[mt][nt][3],                     \
                            af[mt][0], af[mt][1], af[mt][2], af[mt][3],         \
                            bf[nt][0], bf[nt][1]);                              \
        }                                                                       \
    }

/* =====================================================================
 * Kernel 2: QKV projection with fused pack epilogue (R15 verbatim)
 * ===================================================================== */
__global__ void __launch_bounds__(256, 2)
gemm_qkv(const uint32_t* __restrict__ Ah, const uint32_t* __restrict__ Bh,
         uint32_t* __restrict__ qpk, uint32_t* __restrict__ kpk,
         uint32_t* __restrict__ vpk, int M, int K) {
    extern __shared__ uint32_t gsm[];
    int t = threadIdx.x, lane = t & 31, w = t >> 5;
    int m0 = blockIdx.x * 128, n0 = blockIdx.y * 128, b = blockIdx.z;
    const uint32_t* Ab = Ah + m0;
    const uint32_t* Bb = Bh + (long)b * (K >> 1) * NPOS + n0;
    uint32_t sbase = (uint32_t)__cvta_generic_to_shared(gsm);

    int wm = (w >> 2) * 64;
    int wn = (w & 3) * 32;
    int g  = lane >> 2, tg = lane & 3;

    float acc[4][4][4];
    #pragma unroll
    for (int i = 0; i < 4; i++)
        #pragma unroll
        for (int j = 0; j < 4; j++)
            #pragma unroll
            for (int r = 0; r < 4; r++) acc[i][j][r] = 0.f;

    GEMM_MAINLOOP(acc)

    int part = m0 >> 9;
    float qs = (part == 0) ? 0.125f : 1.0f;
    bool evg = (g & 1) == 0;

    #pragma unroll
    for (int mt = 0; mt < 4; mt++) {
        int row0 = m0 + wm + mt * 16 + g;
        int h  = (row0 & 511) >> 6;
        int bh = b * 8 + h;
        #pragma unroll
        for (int nt = 0; nt < 4; nt++) {
            int c0 = n0 + wn + nt * 8 + 2 * tg;
            float v0 = tfr(acc[mt][nt][0]) * qs;
            float v1 = tfr(acc[mt][nt][1]) * qs;
            float v2 = tfr(acc[mt][nt][2]) * qs;
            float v3 = tfr(acc[mt][nt][3]) * qs;
            if (part < 2) {
                float p0 = __shfl_xor_sync(0xffffffffu, v0, 4);
                float p1 = __shfl_xor_sync(0xffffffffu, v1, 4);
                float p2 = __shfl_xor_sync(0xffffffffu, v2, 4);
                float p3 = __shfl_xor_sync(0xffffffffu, v3, 4);
                if (evg) {
                    int dp = (row0 & 63) >> 1;
                    uint32_t* dst = (part == 0 ? qpk : kpk)
                                  + ((long)bh * 32 + dp) * 2048 + c0;
                    *(uint2*)dst = make_uint2(pk_h2(v0, p0), pk_h2(v1, p1));
                    *(uint2*)(dst + 4 * 2048) = make_uint2(pk_h2(v2, p2), pk_h2(v3, p3));
                }
            } else {
                int d0 = row0 & 63;
                int jp = c0 >> 1;
                uint32_t* dst = vpk + ((long)bh * 1024 + jp) * 64 + d0;
                dst[0] = pk_h2(v0, v1);
                dst[8] = pk_h2(v2, v3);
            }
        }
    }
}

/* =====================================================================
 * Kernel 4: output projection (R15 verbatim)
 * ===================================================================== */
__global__ void __launch_bounds__(256, 2)
gemm_f16(const uint32_t* __restrict__ Ah, const uint32_t* __restrict__ Bh,
         float* __restrict__ C, const float* __restrict__ bias,
         int M, int K) {
    extern __shared__ uint32_t gsm[];
    int t = threadIdx.x, lane = t & 31, w = t >> 5;
    int m0 = blockIdx.x * 128, n0 = blockIdx.y * 128, b = blockIdx.z;
    const uint32_t* Ab = Ah + m0;
    const uint32_t* Bb = Bh + (long)b * (K >> 1) * NPOS + n0;
    float*           Cb = C  + (long)b * M * NPOS;
    uint32_t sbase = (uint32_t)__cvta_generic_to_shared(gsm);

    int wm = (w >> 2) * 64;
    int wn = (w & 3) * 32;
    int g  = lane >> 2, tg = lane & 3;

    float acc[4][4][4];
    #pragma unroll
    for (int i = 0; i < 4; i++)
        #pragma unroll
        for (int j = 0; j < 4; j++)
            #pragma unroll
            for (int r = 0; r < 4; r++) acc[i][j][r] = 0.f;

    GEMM_MAINLOOP(acc)

    #pragma unroll
    for (int mt = 0; mt < 4; mt++) {
        int r0 = m0 + wm + mt * 16 + g;
        float b0 = bias ? bias[r0]     : 0.f;
        float b1 = bias ? bias[r0 + 8] : 0.f;
        #pragma unroll
        for (int nt = 0; nt < 4; nt++) {
            int c0 = n0 + wn + nt * 8 + 2 * tg;
            *(float2*)(Cb + (long)r0 * NPOS + c0) =
                make_float2(acc[mt][nt][0] + b0, acc[mt][nt][1] + b0);
            *(float2*)(Cb + (long)(r0 + 8) * NPOS + c0) =
                make_float2(acc[mt][nt][2] + b1, acc[mt][nt][3] + b1);
        }
    }
}

/* =====================================================================
 * Kernel 3: fused FP16 flash attention — 128-query CTAs (256 thr,
 * 8 warps x 16 rows). Per-warp code is R15 VERBATIM (bitwise per row);
 * only block geometry changed: K/V gmem traffic per query HALVES.
 * smem: KH[2][2304] VH[2][2304] PH[32*136] = 13568 words = 54272 B
 *       -> 2 CTAs/SM (reg-limited), 16 warps/SM (same as R15).
 * ===================================================================== */
#define HST  72
#define PHST 136
#define KH_OFF 0
#define VH_OFF (2 * 2304)
#define PH_OFF (4 * 2304)                        /* 9216 */
#define ATTN_SMEM_WORDS (PH_OFF + 32 * PHST)     /* 13568 words = 54272 B */

__global__ void __launch_bounds__(256, 2)
attn_f16(const uint32_t* __restrict__ qpk, const uint32_t* __restrict__ kpk,
         const uint32_t* __restrict__ vpk, uint32_t* __restrict__ aoh) {
    extern __shared__ uint32_t sm4[];
    uint32_t* PH = sm4 + PH_OFF;
    uint32_t sbase = (uint32_t)__cvta_generic_to_shared(sm4);

    int t = threadIdx.x, lane = t & 31, w = t >> 5;   /* w: 0..7 */
    int g = lane >> 2, tg = lane & 3;
    int iw = w * 16;                                  /* warp's 16 query rows */

    int qt = blockIdx.x;                              /* 0..15 */
    int bh = blockIdx.y;                              /* 0..63 */
    int b  = bh >> 3, h = bh & 7;
    int i0 = qt * 128;

    const uint32_t* qb = qpk + (long)bh * 32 * 2048;
    const uint32_t* kb = kpk + (long)bh * 32 * 2048;
    const uint32_t* vb = vpk + (long)bh * 1024 * 64;

    /* combined K+V tile load into buffer p (512 chunks over 256 thr) */
    auto load_kv = [&](int j0, int p) {
        #pragma unroll
        for (int ss = 0; ss < 2; ss++) {
            int c = ss * 256 + t;
            int dp = c >> 4, cw = (c & 15) << 2;
            cpasync16(sbase + (KH_OFF + p * 2304 + dp * HST + cw) * 4,
                      kb + (long)dp * 2048 + j0 + cw);
        }
        #pragma unroll
        for (int ss = 0; ss < 2; ss++) {
            int c = ss * 256 + t;
            int jp = c >> 4, cw = (c & 15) << 2;
            cpasync16(sbase + (VH_OFF + p * 2304 + jp * HST + cw) * 4,
                      vb + ((long)(j0 >> 1) + jp) * 64 + cw);
        }
        CP_COMMIT();
    };

    load_kv(0, 0);
    load_kv(64, 1);

    /* Q fragments: direct gmem gather (R15 formulas, i0 now 128-wide) */
    uint32_t aq[4][4];
    {
        int r0q = i0 + iw + g;
        #pragma unroll
        for (int kbk = 0; kbk < 4; kbk++) {
            const uint32_t* q0 = qb + (long)(kbk * 8 + tg) * 2048 + r0q;
            const uint32_t* q1 = qb + (long)(kbk * 8 + 4 + tg) * 2048 + r0q;
            aq[kbk][0] = q0[0];
            aq[kbk][1] = q0[8];
            aq[kbk][2] = q1[0];
            aq[kbk][3] = q1[8];
        }
    }

    float m_s[2], l_s[2];
    float o[8][4];
    m_s[0] = m_s[1] = -1e30f;
    l_s[0] = l_s[1] = 0.f;
    #pragma unroll
    for (int nt = 0; nt < 8; nt++)
        #pragma unroll
        for (int r = 0; r < 4; r++) o[nt][r] = 0.f;

    const int T = NPOS / 64;
    for (int ti = 0; ti < T; ti++) {
        int p = ti & 1;
        if (ti + 1 < T) { CP_WAIT(1); } else { CP_WAIT(0); }
        __syncthreads();

        const uint32_t* KH = sm4 + KH_OFF + p * 2304;
        const uint32_t* VH = sm4 + VH_OFF + p * 2304;

        /* ---- S = Q^T K : warp 16i x 64j (R15 verbatim) ---- */
        float sa[8][4];
        #pragma unroll
        for (int nt = 0; nt < 8; nt++)
            #pragma unroll
            for (int r = 0; r < 4; r++) sa[nt][r] = 0.f;

        #pragma unroll
        for (int kbk = 0; kbk < 4; kbk++) {
            int q0 = (kbk * 8 + tg) * HST;
            int q1 = (kbk * 8 + 4 + tg) * HST;
            #pragma unroll
            for (int nt = 0; nt < 8; nt++) {
                uint32_t b0 = KH[q0 + nt * 8 + g];
                uint32_t b1 = KH[q1 + nt * 8 + g];
                mma_f16(sa[nt][0], sa[nt][1], sa[nt][2], sa[nt][3],
                        aq[kbk][0], aq[kbk][1], aq[kbk][2], aq[kbk][3],
                        b0, b1);
            }
        }

        /* ---- online softmax (R15 numerics verbatim) ---- */
        {
            float mx0 = -1e30f, mx1 = -1e30f;
            #pragma unroll
            for (int nt = 0; nt < 8; nt++) {
                mx0 = fmaxf(mx0, fmaxf(sa[nt][0], sa[nt][1]));
                mx1 = fmaxf(mx1, fmaxf(sa[nt][2], sa[nt][3]));
            }
            mx0 = fmaxf(mx0, __shfl_xor_sync(0xffffffffu, mx0, 1));
            mx0 = fmaxf(mx0, __shfl_xor_sync(0xffffffffu, mx0, 2));
            mx1 = fmaxf(mx1, __shfl_xor_sync(0xffffffffu, mx1, 1));
            mx1 = fmaxf(mx1, __shfl_xor_sync(0xffffffffu, mx1, 2));
            float mn0 = fmaxf(m_s[0], mx0);
            float mn1 = fmaxf(m_s[1], mx1);
            float s0 = 0.f, s1 = 0.f;
            int r0 = iw + g;
            #pragma unroll
            for (int nt = 0; nt < 8; nt++) {
                float p0 = __expf(sa[nt][0] - mn0);
                float p1 = __expf(sa[nt][1] - mn0);
                float p2 = __expf(sa[nt][2] - mn1);
                float p3 = __expf(sa[nt][3] - mn1);
                s0 += p0 + p1;  s1 += p2 + p3;
                int jp = nt * 4 + tg;
                PH[jp * PHST + r0]     = pk_h2(p0, p1);
                PH[jp * PHST + r0 + 8] = pk_h2(p2, p3);
            }
            s0 += __shfl_xor_sync(0xffffffffu, s0, 1);
            s0 += __shfl_xor_sync(0xffffffffu, s0, 2);
            s1 += __shfl_xor_sync(0xffffffffu, s1, 1);
            s1 += __shfl_xor_sync(0xffffffffu, s1, 2);
            float al0 = __expf(m_s[0] - mn0);
            float al1 = __expf(m_s[1] - mn1);
            l_s[0] = l_s[0] * al0 + s0;  m_s[0] = mn0;
            l_s[1] = l_s[1] * al1 + s1;  m_s[1] = mn1;
            #pragma unroll
            for (int nt = 0; nt < 8; nt++) {
                o[nt][0] *= al0; o[nt][1] *= al0;
                o[nt][2] *= al1; o[nt][3] *= al1;
            }
        }
        __syncwarp();                          /* P columns are warp-local */

        /* ---- O += P V^T : warp 16i x 64d (R15 verbatim) ---- */
        #pragma unroll
        for (int jb = 0; jb < 4; jb++) {
            int r0 = iw + g;
            int pr0 = (jb * 8 + tg) * PHST;
            int pr1 = (jb * 8 + 4 + tg) * PHST;
            int vr0 = (jb * 8 + tg) * HST;
            int vr1 = (jb * 8 + 4 + tg) * HST;
            uint32_t a0 = PH[pr0 + r0];
            uint32_t a1 = PH[pr0 + r0 + 8];
            uint32_t a2 = PH[pr1 + r0];
            uint32_t a3 = PH[pr1 + r0 + 8];
            #pragma unroll
            for (int nt = 0; nt < 8; nt++) {
                uint32_t b0 = VH[vr0 + nt * 8 + g];
                uint32_t b1 = VH[vr1 + nt * 8 + g];
                mma_f16(o[nt][0], o[nt][1], o[nt][2], o[nt][3],
                        a0, a1, a2, a3, b0, b1);
            }
        }
        __syncthreads();                       /* all warps done with buf p */
        if (ti + 2 < T) load_kv((ti + 2) * 64, p);
    }

    /* ---- epilogue: normalize, tf32-round, transpose (stride 136) ---- */
    {
        float inv0 = 1.f / l_s[0], inv1 = 1.f / l_s[1];
        int r0 = iw + g;
        #pragma unroll
        for (int nt = 0; nt < 8; nt++) {
            int d0 = nt * 8 + 2 * tg;
            sm4[d0 * PHST + r0]           = f2tf(o[nt][0] * inv0);
            sm4[(d0 + 1) * PHST + r0]     = f2tf(o[nt][1] * inv0);
            sm4[d0 * PHST + r0 + 8]       = f2tf(o[nt][2] * inv1);
            sm4[(d0 + 1) * PHST + r0 + 8] = f2tf(o[nt][3] * inv1);
        }
    }
    __syncthreads();
    uint32_t* aop = aoh + ((long)b * 256 + (long)h * 32) * NPOS + i0;
    #pragma unroll
    for (int ss = 0; ss < 4; ss++) {
        int lin = ss * 256 + t;                    /* 1024 items */
        int dp = lin >> 5, i4 = (lin & 31) << 2;
        uint4 wv;
        wv.x = pk_h2(__uint_as_float(sm4[(2 * dp) * PHST + i4 + 0]),
                     __uint_as_float(sm4[(2 * dp + 1) * PHST + i4 + 0]));
        wv.y = pk_h2(__uint_as_float(sm4[(2 * dp) * PHST + i4 + 1]),
                     __uint_as_float(sm4[(2 * dp + 1) * PHST + i4 + 1]));
        wv.z = pk_h2(__uint_as_float(sm4[(2 * dp) * PHST + i4 + 2]),
                     __uint_as_float(sm4[(2 * dp + 1) * PHST + i4 + 2]));
        wv.w = pk_h2(__uint_as_float(sm4[(2 * dp) * PHST + i4 + 3]),
                     __uint_as_float(sm4[(2 * dp + 1) * PHST + i4 + 3]));
        *(uint4*)(aop + (long)dp * NPOS + i4) = wv;
    }
}

/* ===================================================================== */
extern "C" void kernel_launch(void* const* d_in, const int* in_sizes, int n_in,
                              void* d_out, int out_size) {
    const float* x    = (const float*)d_in[0];
    const float* g    = (const float*)d_in[1];
    const float* Wqkv = (const float*)d_in[2];
    const float* Wout = (const float*)d_in[3];
    const float* bout = (const float*)d_in[4];
    float* out = (float*)d_out;

    uint32_t *xnh, *aoh, *wqh, *woh, *qpk, *kpk, *vpk;
    cudaGetSymbolAddress((void**)&xnh, g_xnh);
    cudaGetSymbolAddress((void**)&aoh, g_aoh);
    cudaGetSymbolAddress((void**)&wqh, g_wqh);
    cudaGetSymbolAddress((void**)&woh, g_woh);
    cudaGetSymbolAddress((void**)&qpk, g_qpk);
    cudaGetSymbolAddress((void**)&kpk, g_kpk);
    cudaGetSymbolAddress((void**)&vpk, g_vpk);

    /* 0. one-time weight prepack */
    pack_w<<<(QKV_ROWS * 256) / 256, 256>>>(Wqkv, wqh, QKV_ROWS, CDIM);
    pack_w<<<(CDIM * 256) / 256, 256>>>(Wout, woh, CDIM, HIDDEN);

    /* 1. LayerNorm -> packed half2 */
    ln_kernel<<<(BATCH * NPOS) / 64, 512>>>(x, g, xnh);

    /* 2. QKV projection with fused pack epilogue */
    cudaFuncSetAttribute(gemm_qkv,
                         cudaFuncAttributeMaxDynamicSharedMemorySize, GEMM16_SMEM);
    gemm_qkv<<<dim3(QKV_ROWS / 128, NPOS / 128, BATCH), 256, GEMM16_SMEM>>>(
        wqh, xnh, qpk, kpk, vpk, QKV_ROWS, CDIM);

    /* 3. fused fp16 attention (128-query CTAs) */
    size_t smem = ATTN_SMEM_WORDS * sizeof(uint32_t);   /* 54272 B */
    cudaFuncSetAttribute(attn_f16,
                         cudaFuncAttributeMaxDynamicSharedMemorySize, (int)smem);
    attn_f16<<<dim3(NPOS / 128, BATCH * HEADS), 256, smem>>>(qpk, kpk, vpk, aoh);

    /* 4. output projection + bias (fp32 out) */
    cudaFuncSetAttribute(gemm_f16,
                         cudaFuncAttributeMaxDynamicSharedMemorySize, GEMM16_SMEM);
    gemm_f16<<<dim3(HIDDEN / 128, NPOS / 128, BATCH), 256, GEMM16_SMEM>>>(
        woh, aoh, out, bout, HIDDEN, CDIM);
}